// round 3
// baseline (speedup 1.0000x reference)
#include <cuda_runtime.h>
#include <cstdint>

#define HID 200
#define DD  8
#define SB  4           // samples per block
#define NTH 256
#define PAD 12          // padded inner dim for direction buffer (16B-aligned rows)
#define EPSV 0.1f

// Pre-transposed weights (device scratch; no allocation)
__device__ float g_W1T[HID * HID];
__device__ float g_W2T[HID * HID];

__global__ void transposeW(const float* __restrict__ W1, const float* __restrict__ W2) {
    int idx = blockIdx.x * blockDim.x + threadIdx.x;
    if (idx < HID * HID) {
        int r = idx / HID, c = idx % HID;
        g_W1T[c * HID + r] = W1[idx];
        g_W2T[c * HID + r] = W2[idx];
    }
}

typedef unsigned long long u64;

__device__ __forceinline__ u64 pack2(float lo, float hi) {
    u64 r; asm("mov.b64 %0, {%1, %2};" : "=l"(r) : "f"(lo), "f"(hi)); return r;
}
__device__ __forceinline__ float2 unpack2(u64 v) {
    float2 r; asm("mov.b64 {%0, %1}, %2;" : "=f"(r.x), "=f"(r.y) : "l"(v)); return r;
}
__device__ __forceinline__ u64 fma2(u64 a, u64 b, u64 c) {
    u64 d; asm("fma.rn.f32x2 %0, %1, %2, %3;" : "=l"(d) : "l"(a), "l"(b), "l"(c)); return d;
}
__device__ __forceinline__ u64 mul2(u64 a, u64 b) {
    u64 d; asm("mul.rn.f32x2 %0, %1, %2;" : "=l"(d) : "l"(a), "l"(b)); return d;
}

__device__ __forceinline__ float sigm(float x)     { return 1.0f / (1.0f + expf(-x)); }
__device__ __forceinline__ float softplusf(float x){ return fmaxf(x, 0.0f) + log1pf(expf(-fabsf(x))); }

// HVP matvec over the direction buffer: ACC[s][j] += sum_k W[k*HID+tid] * dbuf[s][k][2j..2j+1]
#define HVP_MATVEC(Wptr, ACC)                                                          \
    {                                                                                  \
        _Pragma("unroll")                                                              \
        for (int s = 0; s < SB; s++) { ACC[s][0]=0; ACC[s][1]=0; ACC[s][2]=0; ACC[s][3]=0; } \
        _Pragma("unroll 2")                                                            \
        for (int k = 0; k < HID; k++) {                                                \
            float w = (Wptr)[k * HID + tid];                                           \
            u64 wp = pack2(w, w);                                                      \
            _Pragma("unroll")                                                          \
            for (int s = 0; s < SB; s++) {                                             \
                const ulonglong2* p = reinterpret_cast<const ulonglong2*>(&dbuf[s][k][0]); \
                ulonglong2 q0 = p[0];                                                  \
                ulonglong2 q1 = p[1];                                                  \
                ACC[s][0] = fma2(wp, q0.x, ACC[s][0]);                                 \
                ACC[s][1] = fma2(wp, q0.y, ACC[s][1]);                                 \
                ACC[s][2] = fma2(wp, q1.x, ACC[s][2]);                                 \
                ACC[s][3] = fma2(wp, q1.y, ACC[s][3]);                                 \
            }                                                                          \
        }                                                                              \
    }

// Forward/backward matvec over vecb: ACC[s] += sum_k W[k*HID+tid] * vecb[s][k]
#define VEC_MATVEC(Wptr, ACC)                                                          \
    {                                                                                  \
        _Pragma("unroll 4")                                                            \
        for (int k = 0; k < HID; k++) {                                                \
            float w = (Wptr)[k * HID + tid];                                           \
            _Pragma("unroll")                                                          \
            for (int s = 0; s < SB; s++) ACC[s] = fmaf(vecb[s][k], w, ACC[s]);         \
        }                                                                              \
    }

__global__ void __launch_bounds__(NTH, 2) lnn_kernel(
    const float* __restrict__ z,
    const float* __restrict__ W0, const float* __restrict__ b0,
    const float* __restrict__ W1, const float* __restrict__ b1,
    const float* __restrict__ W2, const float* __restrict__ b2,
    const float* __restrict__ W3,
    float* __restrict__ out, int n)
{
    __shared__ __align__(16) float dbuf[SB][HID][PAD];  // 38400 B: 8-direction tangent buffer
    __shared__ float vecb[SB][HID];                     // ping buffer for fwd/bwd vectors
    __shared__ float shz[SB][16];
    __shared__ float sh_g[SB][16];
    __shared__ float sh_H[SB][8][16];                   // sh_H[s][d][m] = H[8+d][m]

    const int tid  = threadIdx.x;
    const int base = blockIdx.x * SB;
    const bool act = (tid < HID);
    const int warp = tid >> 5, lane = tid & 31;

    // load z (clamped for tail safety)
    for (int i = tid; i < SB * 16; i += NTH) {
        int smp = base + (i >> 4);
        if (smp >= n) smp = n - 1;
        shz[i >> 4][i & 15] = z[smp * 16 + (i & 15)];
    }
    __syncthreads();

    float s1[SB], s2[SB], s3[SB], u1a[SB], u2a[SB], hreg[SB];
    float w3v = 0.0f;

    // ---------- forward ----------
    if (act) {
        float acc[SB]; float bb = b0[tid];
        #pragma unroll
        for (int s = 0; s < SB; s++) acc[s] = bb;
        #pragma unroll
        for (int m = 0; m < 16; m++) {
            float w = W0[m * HID + tid];
            #pragma unroll
            for (int s = 0; s < SB; s++) acc[s] = fmaf(shz[s][m], w, acc[s]);
        }
        #pragma unroll
        for (int s = 0; s < SB; s++) { s1[s] = sigm(acc[s]); vecb[s][tid] = softplusf(acc[s]); }
    }
    __syncthreads();

    if (act) {  // x2 = h1 @ W1 + b1
        float acc[SB]; float bb = b1[tid];
        #pragma unroll
        for (int s = 0; s < SB; s++) acc[s] = bb;
        VEC_MATVEC(W1, acc);
        #pragma unroll
        for (int s = 0; s < SB; s++) { s2[s] = sigm(acc[s]); hreg[s] = softplusf(acc[s]); }
    }
    __syncthreads();
    if (act) {
        #pragma unroll
        for (int s = 0; s < SB; s++) vecb[s][tid] = hreg[s];
    }
    __syncthreads();

    if (act) {  // x3 = h2 @ W2 + b2 ; d3 = W3 * sigma(x3)
        float acc[SB]; float bb = b2[tid];
        #pragma unroll
        for (int s = 0; s < SB; s++) acc[s] = bb;
        VEC_MATVEC(W2, acc);
        w3v = W3[tid];
        #pragma unroll
        for (int s = 0; s < SB; s++) { s3[s] = sigm(acc[s]); hreg[s] = w3v * s3[s]; }
    }
    __syncthreads();
    if (act) {
        #pragma unroll
        for (int s = 0; s < SB; s++) vecb[s][tid] = hreg[s];
    }
    __syncthreads();

    // ---------- backward ----------
    if (act) {  // u2 = W2 @ d3 ; d2 = s2 * u2
        float acc[SB];
        #pragma unroll
        for (int s = 0; s < SB; s++) acc[s] = 0.0f;
        VEC_MATVEC(g_W2T, acc);
        #pragma unroll
        for (int s = 0; s < SB; s++) { u2a[s] = acc[s]; hreg[s] = s2[s] * acc[s]; }
    }
    __syncthreads();
    if (act) {
        #pragma unroll
        for (int s = 0; s < SB; s++) vecb[s][tid] = hreg[s];
    }
    __syncthreads();

    if (act) {  // u1 = W1 @ d2 ; d1 = s1 * u1
        float acc[SB];
        #pragma unroll
        for (int s = 0; s < SB; s++) acc[s] = 0.0f;
        VEC_MATVEC(g_W1T, acc);
        #pragma unroll
        for (int s = 0; s < SB; s++) { u1a[s] = acc[s]; hreg[s] = s1[s] * acc[s]; }
    }
    __syncthreads();
    if (act) {
        #pragma unroll
        for (int s = 0; s < SB; s++) vecb[s][tid] = hreg[s];
    }
    __syncthreads();

    // gradient dots: g[m] = sum_k W0[m,k] * d1[k]   (64 warp-dots)
    for (int idx = warp; idx < SB * 16; idx += 8) {
        int s = idx >> 4, m = idx & 15;
        float a = 0.0f;
        for (int k = lane; k < HID; k += 32) a = fmaf(W0[m * HID + k], vecb[s][k], a);
        #pragma unroll
        for (int off = 16; off > 0; off >>= 1) a += __shfl_xor_sync(0xffffffffu, a, off);
        if (lane == 0) sh_g[s][m] = a;
    }
    __syncthreads();

    // ---------- HVP: 8 directions e_8..e_15 processed together ----------
    // th1 = s1 * t1, t1[d] = W0[8+d, :]
    if (act) {
        float tf[DD];
        #pragma unroll
        for (int d = 0; d < DD; d++) tf[d] = W0[(DD + d) * HID + tid];
        #pragma unroll
        for (int s = 0; s < SB; s++) {
            #pragma unroll
            for (int d = 0; d < DD; d++) dbuf[s][tid][d] = s1[s] * tf[d];
        }
    }
    __syncthreads();

    u64 a2[SB][4];   // t2 (kept in registers until delta-d2)
    if (act) { HVP_MATVEC(W1, a2); }
    __syncthreads();
    if (act) {  // th2 = s2 * t2
        #pragma unroll
        for (int s = 0; s < SB; s++) {
            u64 sp = pack2(s2[s], s2[s]);
            #pragma unroll
            for (int j = 0; j < 4; j++)
                *reinterpret_cast<u64*>(&dbuf[s][tid][2 * j]) = mul2(sp, a2[s][j]);
        }
    }
    __syncthreads();

    u64 aw[SB][4];
    if (act) { HVP_MATVEC(W2, aw); }   // t3
    __syncthreads();
    if (act) {  // delta-d3 = W3 * s3*(1-s3) * t3
        #pragma unroll
        for (int s = 0; s < SB; s++) {
            float c = w3v * s3[s] * (1.0f - s3[s]);
            u64 cp = pack2(c, c);
            #pragma unroll
            for (int j = 0; j < 4; j++)
                *reinterpret_cast<u64*>(&dbuf[s][tid][2 * j]) = mul2(cp, aw[s][j]);
        }
    }
    __syncthreads();

    if (act) { HVP_MATVEC(g_W2T, aw); }   // r2 = W2 @ delta-d3
    __syncthreads();
    if (act) {  // delta-d2 = s2*r2 + s2*(1-s2)*u2*t2
        #pragma unroll
        for (int s = 0; s < SB; s++) {
            u64 A = pack2(s2[s], s2[s]);
            float sp2u2 = s2[s] * (1.0f - s2[s]) * u2a[s];
            u64 B = pack2(sp2u2, sp2u2);
            #pragma unroll
            for (int j = 0; j < 4; j++)
                *reinterpret_cast<u64*>(&dbuf[s][tid][2 * j]) = fma2(B, a2[s][j], mul2(A, aw[s][j]));
        }
    }
    __syncthreads();

    if (act) { HVP_MATVEC(g_W1T, aw); }   // r1 = W1 @ delta-d2
    __syncthreads();
    if (act) {  // delta-d1 = s1*r1 + s1*(1-s1)*u1*t1
        float tf[DD];
        #pragma unroll
        for (int d = 0; d < DD; d++) tf[d] = W0[(DD + d) * HID + tid];
        #pragma unroll
        for (int s = 0; s < SB; s++) {
            float sp1u1 = s1[s] * (1.0f - s1[s]) * u1a[s];
            #pragma unroll
            for (int j = 0; j < 4; j++) {
                float2 rr = unpack2(aw[s][j]);
                dbuf[s][tid][2 * j]     = fmaf(s1[s], rr.x, sp1u1 * tf[2 * j]);
                dbuf[s][tid][2 * j + 1] = fmaf(s1[s], rr.y, sp1u1 * tf[2 * j + 1]);
            }
        }
    }
    __syncthreads();

    // Hessian-row dots: H[8+d][m] = sum_k W0[m,k] * delta-d1[d][k]   (512 warp-dots)
    for (int idx = warp; idx < SB * 128; idx += 8) {
        int s = idx >> 7;
        int r = idx & 127;
        int d = r >> 4, m = r & 15;
        float a = 0.0f;
        for (int k = lane; k < HID; k += 32) a = fmaf(W0[m * HID + k], dbuf[s][k][d], a);
        #pragma unroll
        for (int off = 16; off > 0; off >>= 1) a += __shfl_xor_sync(0xffffffffu, a, off);
        if (lane == 0) sh_H[s][d][m] = a;
    }
    __syncthreads();

    // ---------- per-sample 8x8 solve + output ----------
    if (tid < SB && base + tid < n) {
        const int s = tid;
        float Mt[DD][DD], Fv[DD], av[DD], vv[DD];
        #pragma unroll
        for (int c = 0; c < DD; c++) vv[c] = shz[s][DD + c];
        for (int r = 0; r < DD; r++)
            for (int c = 0; c < DD; c++)
                Mt[r][c] = sh_H[s][r][DD + c] + ((r == c) ? 2.0f * EPSV : 0.0f);
        for (int p = 0; p < DD; p++) {
            float f = sh_g[s][p];
            for (int c = 0; c < DD; c++) f -= sh_H[s][p][c] * vv[c];
            Fv[p] = f;
        }
        // Gaussian elimination with partial pivoting
        for (int col = 0; col < DD; col++) {
            int piv = col; float best = fabsf(Mt[col][col]);
            for (int r = col + 1; r < DD; r++) {
                float m = fabsf(Mt[r][col]);
                if (m > best) { best = m; piv = r; }
            }
            if (piv != col) {
                for (int c = col; c < DD; c++) { float t = Mt[col][c]; Mt[col][c] = Mt[piv][c]; Mt[piv][c] = t; }
                float t = Fv[col]; Fv[col] = Fv[piv]; Fv[piv] = t;
            }
            float inv = 1.0f / Mt[col][col];
            for (int r = col + 1; r < DD; r++) {
                float fac = Mt[r][col] * inv;
                for (int c = col; c < DD; c++) Mt[r][c] -= fac * Mt[col][c];
                Fv[r] -= fac * Fv[col];
            }
        }
        for (int r = DD - 1; r >= 0; r--) {
            float x = Fv[r];
            for (int c = r + 1; c < DD; c++) x -= Mt[r][c] * av[c];
            av[r] = x / Mt[r][r];
        }
        const int gi = (base + s) * 16;
        #pragma unroll
        for (int j = 0; j < DD; j++) out[gi + j] = vv[j];
        #pragma unroll
        for (int j = 0; j < DD; j++) out[gi + DD + j] = av[j];
    }
}

extern "C" void kernel_launch(void* const* d_in, const int* in_sizes, int n_in,
                              void* d_out, int out_size) {
    const float* z  = (const float*)d_in[1];
    const float* W0 = (const float*)d_in[2];
    const float* b0 = (const float*)d_in[3];
    const float* W1 = (const float*)d_in[4];
    const float* b1 = (const float*)d_in[5];
    const float* W2 = (const float*)d_in[6];
    const float* b2 = (const float*)d_in[7];
    const float* W3 = (const float*)d_in[8];
    float* out = (float*)d_out;

    const int n = in_sizes[1] / 16;

    transposeW<<<(HID * HID + 255) / 256, 256>>>(W1, W2);

    const int blocks = (n + SB - 1) / SB;
    lnn_kernel<<<blocks, NTH>>>(z, W0, b0, W1, b1, W2, b2, W3, out, n);
}

// round 5
// speedup vs baseline: 1.1706x; 1.1706x over previous
#include <cuda_runtime.h>
#include <cstdint>

#define HID 200
#define DD  8
#define SB  4           // samples per block
#define NTH 256
#define PAD 12          // padded inner dim for direction buffer (16B-aligned rows)
#define EPSV 0.1f

// Pre-transposed weights (device scratch; no allocation)
__device__ float g_W1T[HID * HID];
__device__ float g_W2T[HID * HID];

__global__ void transposeW(const float* __restrict__ W1, const float* __restrict__ W2) {
    int idx = blockIdx.x * blockDim.x + threadIdx.x;
    if (idx < HID * HID) {
        int r = idx / HID, c = idx % HID;
        g_W1T[c * HID + r] = W1[idx];
        g_W2T[c * HID + r] = W2[idx];
    }
}

typedef unsigned long long u64;

__device__ __forceinline__ u64 pack2(float lo, float hi) {
    u64 r; asm("mov.b64 %0, {%1, %2};" : "=l"(r) : "f"(lo), "f"(hi)); return r;
}
__device__ __forceinline__ float2 unpack2(u64 v) {
    float2 r; asm("mov.b64 {%0, %1}, %2;" : "=f"(r.x), "=f"(r.y) : "l"(v)); return r;
}
__device__ __forceinline__ u64 fma2(u64 a, u64 b, u64 c) {
    u64 d; asm("fma.rn.f32x2 %0, %1, %2, %3;" : "=l"(d) : "l"(a), "l"(b), "l"(c)); return d;
}
__device__ __forceinline__ u64 mul2(u64 a, u64 b) {
    u64 d; asm("mul.rn.f32x2 %0, %1, %2;" : "=l"(d) : "l"(a), "l"(b)); return d;
}

__device__ __forceinline__ float sigm(float x)     { return 1.0f / (1.0f + expf(-x)); }
__device__ __forceinline__ float softplusf(float x){ return fmaxf(x, 0.0f) + log1pf(expf(-fabsf(x))); }

// Fused matvec: one pass over W computes BOTH the scalar (fwd/bwd) matvec from
// vecb and the 8-direction HVP matvec from dbuf, sharing the weight load.
// VACC[s]   += sum_k W[k*HID+tid] * vecb[s][k]
// HACC[s][j]+= sum_k W[k*HID+tid] * dbuf[s][k][2j..2j+1]   (packed f32x2)
#define FUSED_MATVEC(Wptr, VACC, HACC)                                                 \
    {                                                                                  \
        _Pragma("unroll 2")                                                            \
        for (int k = 0; k < HID; k++) {                                                \
            float w = (Wptr)[k * HID + tid];                                           \
            u64 wp = pack2(w, w);                                                      \
            _Pragma("unroll")                                                          \
            for (int s = 0; s < SB; s++) {                                             \
                VACC[s] = fmaf(vecb[s][k], w, VACC[s]);                                \
                const ulonglong2* p = reinterpret_cast<const ulonglong2*>(&dbuf[s][k][0]); \
                ulonglong2 q0 = p[0];                                                  \
                ulonglong2 q1 = p[1];                                                  \
                HACC[s][0] = fma2(wp, q0.x, HACC[s][0]);                               \
                HACC[s][1] = fma2(wp, q0.y, HACC[s][1]);                               \
                HACC[s][2] = fma2(wp, q1.x, HACC[s][2]);                               \
                HACC[s][3] = fma2(wp, q1.y, HACC[s][3]);                               \
            }                                                                          \
        }                                                                              \
    }

__global__ void __launch_bounds__(NTH, 2) lnn_kernel(
    const float* __restrict__ z,
    const float* __restrict__ W0, const float* __restrict__ b0,
    const float* __restrict__ W1, const float* __restrict__ b1,
    const float* __restrict__ W2, const float* __restrict__ b2,
    const float* __restrict__ W3,
    float* __restrict__ out, int n)
{
    __shared__ __align__(16) float dbuf[SB][HID][PAD];  // 38400 B: 8-direction tangent buffer
    __shared__ float vecb[SB][HID];                     // ping buffer for fwd/bwd vectors
    __shared__ float shz[SB][16];
    __shared__ float sh_g[SB][16];
    __shared__ float sh_H[SB][8][16];                   // sh_H[s][d][m] = H[8+d][m]

    const int tid  = threadIdx.x;
    const int base = blockIdx.x * SB;
    const bool act = (tid < HID);
    const int warp = tid >> 5, lane = tid & 31;

    // load z (clamped for tail safety)
    for (int i = tid; i < SB * 16; i += NTH) {
        int smp = base + (i >> 4);
        if (smp >= n) smp = n - 1;
        shz[i >> 4][i & 15] = z[smp * 16 + (i & 15)];
    }
    __syncthreads();

    float s1[SB], s2[SB], s3[SB], u2a[SB];
    float w3v = 0.0f;
    u64 a2[SB][4];   // t2, kept live until delta-d2
    u64 aw[SB][4];   // t3 / r2 / r1 (reused)

    // ---------- phase 0: layer-0 forward + tangent seed ----------
    // x1 = z @ W0 + b0 ; h1 -> vecb ; th1[d] = s1 * W0[8+d,:] -> dbuf
    if (act) {
        float acc[SB]; float bb = b0[tid];
        float tf[DD];
        #pragma unroll
        for (int s = 0; s < SB; s++) acc[s] = bb;
        #pragma unroll
        for (int m = 0; m < 16; m++) {
            float w = W0[m * HID + tid];
            if (m >= DD) tf[m - DD] = w;       // rows 8..15 double as tangent seeds
            #pragma unroll
            for (int s = 0; s < SB; s++) acc[s] = fmaf(shz[s][m], w, acc[s]);
        }
        #pragma unroll
        for (int s = 0; s < SB; s++) {
            s1[s] = sigm(acc[s]);
            vecb[s][tid] = softplusf(acc[s]);
            #pragma unroll
            for (int d = 0; d < DD; d++) dbuf[s][tid][d] = s1[s] * tf[d];
        }
    }
    __syncthreads();

    // ---------- phase 1: stream W1 (fwd x2 + HVP t2) ----------
    float vacc[SB];
    if (act) {
        float bb = b1[tid];
        #pragma unroll
        for (int s = 0; s < SB; s++) {
            vacc[s] = bb;
            a2[s][0] = 0; a2[s][1] = 0; a2[s][2] = 0; a2[s][3] = 0;
        }
        FUSED_MATVEC(W1, vacc, a2);
    }
    __syncthreads();
    if (act) {  // h2 -> vecb ; th2 = s2*t2 -> dbuf
        #pragma unroll
        for (int s = 0; s < SB; s++) {
            s2[s] = sigm(vacc[s]);
            vecb[s][tid] = softplusf(vacc[s]);
            u64 sp = pack2(s2[s], s2[s]);
            #pragma unroll
            for (int j = 0; j < 4; j++)
                *reinterpret_cast<u64*>(&dbuf[s][tid][2 * j]) = mul2(sp, a2[s][j]);
        }
    }
    __syncthreads();

    // ---------- phase 2: stream W2 (fwd x3 + HVP t3) ----------
    if (act) {
        float bb = b2[tid];
        #pragma unroll
        for (int s = 0; s < SB; s++) {
            vacc[s] = bb;
            aw[s][0] = 0; aw[s][1] = 0; aw[s][2] = 0; aw[s][3] = 0;
        }
        FUSED_MATVEC(W2, vacc, aw);
        w3v = W3[tid];
    }
    __syncthreads();
    if (act) {  // d3 = w3*s3 -> vecb ; delta-d3 = w3*s3*(1-s3)*t3 -> dbuf
        #pragma unroll
        for (int s = 0; s < SB; s++) {
            s3[s] = sigm(vacc[s]);
            vecb[s][tid] = w3v * s3[s];
            float c = w3v * s3[s] * (1.0f - s3[s]);
            u64 cp = pack2(c, c);
            #pragma unroll
            for (int j = 0; j < 4; j++)
                *reinterpret_cast<u64*>(&dbuf[s][tid][2 * j]) = mul2(cp, aw[s][j]);
        }
    }
    __syncthreads();

    // ---------- phase 3: stream W2^T (bwd u2 + HVP r2) ----------
    if (act) {
        #pragma unroll
        for (int s = 0; s < SB; s++) {
            vacc[s] = 0.0f;
            aw[s][0] = 0; aw[s][1] = 0; aw[s][2] = 0; aw[s][3] = 0;
        }
        FUSED_MATVEC(g_W2T, vacc, aw);
    }
    __syncthreads();
    if (act) {  // d2 = s2*u2 -> vecb ; delta-d2 = s2*r2 + s2*(1-s2)*u2*t2 -> dbuf
        #pragma unroll
        for (int s = 0; s < SB; s++) {
            u2a[s] = vacc[s];
            vecb[s][tid] = s2[s] * vacc[s];
            u64 A = pack2(s2[s], s2[s]);
            float sp2u2 = s2[s] * (1.0f - s2[s]) * vacc[s];
            u64 B = pack2(sp2u2, sp2u2);
            #pragma unroll
            for (int j = 0; j < 4; j++)
                *reinterpret_cast<u64*>(&dbuf[s][tid][2 * j]) = fma2(B, a2[s][j], mul2(A, aw[s][j]));
        }
    }
    __syncthreads();

    // ---------- phase 4: stream W1^T (bwd u1 + HVP r1) ----------
    if (act) {
        #pragma unroll
        for (int s = 0; s < SB; s++) {
            vacc[s] = 0.0f;
            aw[s][0] = 0; aw[s][1] = 0; aw[s][2] = 0; aw[s][3] = 0;
        }
        FUSED_MATVEC(g_W1T, vacc, aw);
    }
    __syncthreads();
    if (act) {  // d1 = s1*u1 -> vecb ; delta-d1 = s1*r1 + s1*(1-s1)*u1*t1 -> dbuf
        float tf[DD];
        #pragma unroll
        for (int d = 0; d < DD; d++) tf[d] = W0[(DD + d) * HID + tid];  // L1 hit
        #pragma unroll
        for (int s = 0; s < SB; s++) {
            vecb[s][tid] = s1[s] * vacc[s];
            float sp1u1 = s1[s] * (1.0f - s1[s]) * vacc[s];
            #pragma unroll
            for (int j = 0; j < 4; j++) {
                float2 rr = unpack2(aw[s][j]);
                dbuf[s][tid][2 * j]     = fmaf(s1[s], rr.x, sp1u1 * tf[2 * j]);
                dbuf[s][tid][2 * j + 1] = fmaf(s1[s], rr.y, sp1u1 * tf[2 * j + 1]);
            }
        }
    }
    __syncthreads();

    // ---------- final dots ----------
    // gradient: g[m] = sum_k W0[m,k] * d1[k]   (64 warp-dots)
    for (int idx = warp; idx < SB * 16; idx += 8) {
        int s = idx >> 4, m = idx & 15;
        float a = 0.0f;
        for (int k = lane; k < HID; k += 32) a = fmaf(W0[m * HID + k], vecb[s][k], a);
        #pragma unroll
        for (int off = 16; off > 0; off >>= 1) a += __shfl_xor_sync(0xffffffffu, a, off);
        if (lane == 0) sh_g[s][m] = a;
    }
    // Hessian rows: H[8+d][m] = sum_k W0[m,k] * delta-d1[d][k]   (512 warp-dots)
    for (int idx = warp; idx < SB * 128; idx += 8) {
        int s = idx >> 7;
        int r = idx & 127;
        int d = r >> 4, m = r & 15;
        float a = 0.0f;
        for (int k = lane; k < HID; k += 32) a = fmaf(W0[m * HID + k], dbuf[s][k][d], a);
        #pragma unroll
        for (int off = 16; off > 0; off >>= 1) a += __shfl_xor_sync(0xffffffffu, a, off);
        if (lane == 0) sh_H[s][d][m] = a;
    }
    __syncthreads();

    // ---------- per-sample 8x8 solve + output ----------
    if (tid < SB && base + tid < n) {
        const int s = tid;
        float Mt[DD][DD], Fv[DD], av[DD], vv[DD];
        #pragma unroll
        for (int c = 0; c < DD; c++) vv[c] = shz[s][DD + c];
        for (int r = 0; r < DD; r++)
            for (int c = 0; c < DD; c++)
                Mt[r][c] = sh_H[s][r][DD + c] + ((r == c) ? 2.0f * EPSV : 0.0f);
        for (int p = 0; p < DD; p++) {
            float f = sh_g[s][p];
            for (int c = 0; c < DD; c++) f -= sh_H[s][p][c] * vv[c];
            Fv[p] = f;
        }
        // Gaussian elimination with partial pivoting
        for (int col = 0; col < DD; col++) {
            int piv = col; float best = fabsf(Mt[col][col]);
            for (int r = col + 1; r < DD; r++) {
                float m = fabsf(Mt[r][col]);
                if (m > best) { best = m; piv = r; }
            }
            if (piv != col) {
                for (int c = col; c < DD; c++) { float t = Mt[col][c]; Mt[col][c] = Mt[piv][c]; Mt[piv][c] = t; }
                float t = Fv[col]; Fv[col] = Fv[piv]; Fv[piv] = t;
            }
            float inv = 1.0f / Mt[col][col];
            for (int r = col + 1; r < DD; r++) {
                float fac = Mt[r][col] * inv;
                for (int c = col; c < DD; c++) Mt[r][c] -= fac * Mt[col][c];
                Fv[r] -= fac * Fv[col];
            }
        }
        for (int r = DD - 1; r >= 0; r--) {
            float x = Fv[r];
            for (int c = r + 1; c < DD; c++) x -= Mt[r][c] * av[c];
            av[r] = x / Mt[r][r];
        }
        const int gi = (base + s) * 16;
        #pragma unroll
        for (int j = 0; j < DD; j++) out[gi + j] = vv[j];
        #pragma unroll
        for (int j = 0; j < DD; j++) out[gi + DD + j] = av[j];
    }
}

extern "C" void kernel_launch(void* const* d_in, const int* in_sizes, int n_in,
                              void* d_out, int out_size) {
    const float* z  = (const float*)d_in[1];
    const float* W0 = (const float*)d_in[2];
    const float* b0 = (const float*)d_in[3];
    const float* W1 = (const float*)d_in[4];
    const float* b1 = (const float*)d_in[5];
    const float* W2 = (const float*)d_in[6];
    const float* b2 = (const float*)d_in[7];
    const float* W3 = (const float*)d_in[8];
    float* out = (float*)d_out;

    const int n = in_sizes[1] / 16;

    transposeW<<<(HID * HID + 255) / 256, 256>>>(W1, W2);

    const int blocks = (n + SB - 1) / SB;
    lnn_kernel<<<blocks, NTH>>>(z, W0, b0, W1, b1, W2, b2, W3, out, n);
}

// round 8
// speedup vs baseline: 1.2102x; 1.0338x over previous
#include <cuda_runtime.h>
#include <cstdint>

#define HID 200
#define DD  8
#define SB  2           // samples per block
#define NTH 256
#define PAD 12          // padded inner dim for direction buffer (16B-aligned rows)
#define EPSV 0.1f

// Pre-transposed weights (device scratch; no allocation)
__device__ float g_W1T[HID * HID];
__device__ float g_W2T[HID * HID];

__global__ void transposeW(const float* __restrict__ W1, const float* __restrict__ W2) {
    int idx = blockIdx.x * blockDim.x + threadIdx.x;
    if (idx < HID * HID) {
        int r = idx / HID, c = idx % HID;
        g_W1T[c * HID + r] = W1[idx];
        g_W2T[c * HID + r] = W2[idx];
    }
}

typedef unsigned long long u64;

__device__ __forceinline__ u64 pack2(float lo, float hi) {
    u64 r; asm("mov.b64 %0, {%1, %2};" : "=l"(r) : "f"(lo), "f"(hi)); return r;
}
__device__ __forceinline__ float2 unpack2(u64 v) {
    float2 r; asm("mov.b64 {%0, %1}, %2;" : "=f"(r.x), "=f"(r.y) : "l"(v)); return r;
}
__device__ __forceinline__ u64 fma2(u64 a, u64 b, u64 c) {
    u64 d; asm("fma.rn.f32x2 %0, %1, %2, %3;" : "=l"(d) : "l"(a), "l"(b), "l"(c)); return d;
}
__device__ __forceinline__ u64 mul2(u64 a, u64 b) {
    u64 d; asm("mul.rn.f32x2 %0, %1, %2;" : "=l"(d) : "l"(a), "l"(b)); return d;
}

__device__ __forceinline__ float sigm(float x)     { return 1.0f / (1.0f + expf(-x)); }
__device__ __forceinline__ float softplusf(float x){ return fmaxf(x, 0.0f) + log1pf(expf(-fabsf(x))); }

// Fused matvec: one pass over W computes BOTH the scalar (fwd/bwd) matvec from
// vecb and the 8-direction HVP matvec from dbuf, sharing the weight load.
// unroll 4 -> 4 weight LDGs in flight per warp (hide L2 latency).
#define FUSED_MATVEC(Wptr, VACC, HACC)                                                 \
    {                                                                                  \
        _Pragma("unroll 4")                                                            \
        for (int k = 0; k < HID; k++) {                                                \
            float w = (Wptr)[k * HID + tid];                                           \
            u64 wp = pack2(w, w);                                                      \
            _Pragma("unroll")                                                          \
            for (int s = 0; s < SB; s++) {                                             \
                VACC[s] = fmaf(vecb[s][k], w, VACC[s]);                                \
                const ulonglong2* p = reinterpret_cast<const ulonglong2*>(&dbuf[s][k][0]); \
                ulonglong2 q0 = p[0];                                                  \
                ulonglong2 q1 = p[1];                                                  \
                HACC[s][0] = fma2(wp, q0.x, HACC[s][0]);                               \
                HACC[s][1] = fma2(wp, q0.y, HACC[s][1]);                               \
                HACC[s][2] = fma2(wp, q1.x, HACC[s][2]);                               \
                HACC[s][3] = fma2(wp, q1.y, HACC[s][3]);                               \
            }                                                                          \
        }                                                                              \
    }

__global__ void __launch_bounds__(NTH, 3) lnn_kernel(
    const float* __restrict__ z,
    const float* __restrict__ W0, const float* __restrict__ b0,
    const float* __restrict__ W1, const float* __restrict__ b1,
    const float* __restrict__ W2, const float* __restrict__ b2,
    const float* __restrict__ W3,
    float* __restrict__ out, int n)
{
    __shared__ __align__(16) float dbuf[SB][HID][PAD];  // 19200 B: 8-direction tangent buffer
    __shared__ float vecb[SB][HID];                     // ping buffer for fwd/bwd vectors
    __shared__ float shz[SB][16];
    __shared__ float sh_g[SB][16];
    __shared__ float sh_H[SB][8][16];                   // sh_H[s][d][m] = H[8+d][m]

    const int tid  = threadIdx.x;
    const int base = blockIdx.x * SB;
    const bool act = (tid < HID);
    const int warp = tid >> 5, lane = tid & 31;

    // load z (clamped for tail safety)
    for (int i = tid; i < SB * 16; i += NTH) {
        int smp = base + (i >> 4);
        if (smp >= n) smp = n - 1;
        shz[i >> 4][i & 15] = z[smp * 16 + (i & 15)];
    }
    __syncthreads();

    float s1[SB], s2[SB], s3[SB];
    float w3v = 0.0f;
    u64 a2[SB][4];   // t2, kept live until delta-d2
    u64 aw[SB][4];   // t3 / r2 / r1 (reused)

    // ---------- phase 0: layer-0 forward + tangent seed ----------
    if (act) {
        float acc[SB]; float bb = b0[tid];
        float tf[DD];
        #pragma unroll
        for (int s = 0; s < SB; s++) acc[s] = bb;
        #pragma unroll
        for (int m = 0; m < 16; m++) {
            float w = W0[m * HID + tid];
            if (m >= DD) tf[m - DD] = w;       // rows 8..15 double as tangent seeds
            #pragma unroll
            for (int s = 0; s < SB; s++) acc[s] = fmaf(shz[s][m], w, acc[s]);
        }
        #pragma unroll
        for (int s = 0; s < SB; s++) {
            s1[s] = sigm(acc[s]);
            vecb[s][tid] = softplusf(acc[s]);
            #pragma unroll
            for (int d = 0; d < DD; d++) dbuf[s][tid][d] = s1[s] * tf[d];
        }
    }
    __syncthreads();

    // ---------- phase 1: stream W1 (fwd x2 + HVP t2) ----------
    float vacc[SB];
    if (act) {
        float bb = b1[tid];
        #pragma unroll
        for (int s = 0; s < SB; s++) {
            vacc[s] = bb;
            a2[s][0] = 0; a2[s][1] = 0; a2[s][2] = 0; a2[s][3] = 0;
        }
        FUSED_MATVEC(W1, vacc, a2);
    }
    __syncthreads();
    if (act) {  // h2 -> vecb ; th2 = s2*t2 -> dbuf
        #pragma unroll
        for (int s = 0; s < SB; s++) {
            s2[s] = sigm(vacc[s]);
            vecb[s][tid] = softplusf(vacc[s]);
            u64 sp = pack2(s2[s], s2[s]);
            #pragma unroll
            for (int j = 0; j < 4; j++)
                *reinterpret_cast<u64*>(&dbuf[s][tid][2 * j]) = mul2(sp, a2[s][j]);
        }
    }
    __syncthreads();

    // ---------- phase 2: stream W2 (fwd x3 + HVP t3) ----------
    if (act) {
        float bb = b2[tid];
        #pragma unroll
        for (int s = 0; s < SB; s++) {
            vacc[s] = bb;
            aw[s][0] = 0; aw[s][1] = 0; aw[s][2] = 0; aw[s][3] = 0;
        }
        FUSED_MATVEC(W2, vacc, aw);
        w3v = W3[tid];
    }
    __syncthreads();
    if (act) {  // d3 = w3*s3 -> vecb ; delta-d3 = w3*s3*(1-s3)*t3 -> dbuf
        #pragma unroll
        for (int s = 0; s < SB; s++) {
            s3[s] = sigm(vacc[s]);
            vecb[s][tid] = w3v * s3[s];
            float c = w3v * s3[s] * (1.0f - s3[s]);
            u64 cp = pack2(c, c);
            #pragma unroll
            for (int j = 0; j < 4; j++)
                *reinterpret_cast<u64*>(&dbuf[s][tid][2 * j]) = mul2(cp, aw[s][j]);
        }
    }
    __syncthreads();

    // ---------- phase 3: stream W2^T (bwd u2 + HVP r2) ----------
    if (act) {
        #pragma unroll
        for (int s = 0; s < SB; s++) {
            vacc[s] = 0.0f;
            aw[s][0] = 0; aw[s][1] = 0; aw[s][2] = 0; aw[s][3] = 0;
        }
        FUSED_MATVEC(g_W2T, vacc, aw);
    }
    __syncthreads();
    if (act) {  // d2 = s2*u2 -> vecb ; delta-d2 = s2*r2 + s2*(1-s2)*u2*t2 -> dbuf
        #pragma unroll
        for (int s = 0; s < SB; s++) {
            vecb[s][tid] = s2[s] * vacc[s];
            u64 A = pack2(s2[s], s2[s]);
            float sp2u2 = s2[s] * (1.0f - s2[s]) * vacc[s];
            u64 B = pack2(sp2u2, sp2u2);
            #pragma unroll
            for (int j = 0; j < 4; j++)
                *reinterpret_cast<u64*>(&dbuf[s][tid][2 * j]) = fma2(B, a2[s][j], mul2(A, aw[s][j]));
        }
    }
    __syncthreads();

    // ---------- phase 4: stream W1^T (bwd u1 + HVP r1) ----------
    if (act) {
        #pragma unroll
        for (int s = 0; s < SB; s++) {
            vacc[s] = 0.0f;
            aw[s][0] = 0; aw[s][1] = 0; aw[s][2] = 0; aw[s][3] = 0;
        }
        FUSED_MATVEC(g_W1T, vacc, aw);
    }
    __syncthreads();
    if (act) {  // d1 = s1*u1 -> vecb ; delta-d1 = s1*r1 + s1*(1-s1)*u1*t1 -> dbuf
        float tf[DD];
        #pragma unroll
        for (int d = 0; d < DD; d++) tf[d] = W0[(DD + d) * HID + tid];  // L1/L2 hit
        #pragma unroll
        for (int s = 0; s < SB; s++) {
            vecb[s][tid] = s1[s] * vacc[s];
            float sp1u1 = s1[s] * (1.0f - s1[s]) * vacc[s];
            #pragma unroll
            for (int j = 0; j < 4; j++) {
                float2 rr = unpack2(aw[s][j]);
                dbuf[s][tid][2 * j]     = fmaf(s1[s], rr.x, sp1u1 * tf[2 * j]);
                dbuf[s][tid][2 * j + 1] = fmaf(s1[s], rr.y, sp1u1 * tf[2 * j + 1]);
            }
        }
    }
    __syncthreads();

    // ---------- final dots ----------
    // gradient: g[m] = sum_k W0[m,k] * d1[k]   (SB*16 warp-dots)
    for (int idx = warp; idx < SB * 16; idx += 8) {
        int s = idx >> 4, m = idx & 15;
        float a = 0.0f;
        for (int k = lane; k < HID; k += 32) a = fmaf(W0[m * HID + k], vecb[s][k], a);
        #pragma unroll
        for (int off = 16; off > 0; off >>= 1) a += __shfl_xor_sync(0xffffffffu, a, off);
        if (lane == 0) sh_g[s][m] = a;
    }
    // Hessian rows: H[8+d][m] = sum_k W0[m,k] * delta-d1[d][k]   (SB*128 warp-dots)
    for (int idx = warp; idx < SB * 128; idx += 8) {
        int s = idx >> 7;
        int r = idx & 127;
        int d = r >> 4, m = r & 15;
        float a = 0.0f;
        for (int k = lane; k < HID; k += 32) a = fmaf(W0[m * HID + k], dbuf[s][k][d], a);
        #pragma unroll
        for (int off = 16; off > 0; off >>= 1) a += __shfl_xor_sync(0xffffffffu, a, off);
        if (lane == 0) sh_H[s][d][m] = a;
    }
    __syncthreads();

    // ---------- per-sample 8x8 solve + output ----------
    if (tid < SB && base + tid < n) {
        const int s = tid;
        float Mt[DD][DD], Fv[DD], av[DD], vv[DD];
        #pragma unroll
        for (int c = 0; c < DD; c++) vv[c] = shz[s][DD + c];
        for (int r = 0; r < DD; r++)
            for (int c = 0; c < DD; c++)
                Mt[r][c] = sh_H[s][r][DD + c] + ((r == c) ? 2.0f * EPSV : 0.0f);
        for (int p = 0; p < DD; p++) {
            float f = sh_g[s][p];
            for (int c = 0; c < DD; c++) f -= sh_H[s][p][c] * vv[c];
            Fv[p] = f;
        }
        // Gaussian elimination with partial pivoting
        for (int col = 0; col < DD; col++) {
            int piv = col; float best = fabsf(Mt[col][col]);
            for (int r = col + 1; r < DD; r++) {
                float m = fabsf(Mt[r][col]);
                if (m > best) { best = m; piv = r; }
            }
            if (piv != col) {
                for (int c = col; c < DD; c++) { float t = Mt[col][c]; Mt[col][c] = Mt[piv][c]; Mt[piv][c] = t; }
                float t = Fv[col]; Fv[col] = Fv[piv]; Fv[piv] = t;
            }
            float inv = 1.0f / Mt[col][col];
            for (int r = col + 1; r < DD; r++) {
                float fac = Mt[r][col] * inv;
                for (int c = col; c < DD; c++) Mt[r][c] -= fac * Mt[col][c];
                Fv[r] -= fac * Fv[col];
            }
        }
        for (int r = DD - 1; r >= 0; r--) {
            float x = Fv[r];
            for (int c = r + 1; c < DD; c++) x -= Mt[r][c] * av[c];
            av[r] = x / Mt[r][r];
        }
        const int gi = (base + s) * 16;
        #pragma unroll
        for (int j = 0; j < DD; j++) out[gi + j] = vv[j];
        #pragma unroll
        for (int j = 0; j < DD; j++) out[gi + DD + j] = av[j];
    }
}

extern "C" void kernel_launch(void* const* d_in, const int* in_sizes, int n_in,
                              void* d_out, int out_size) {
    const float* z  = (const float*)d_in[1];
    const float* W0 = (const float*)d_in[2];
    const float* b0 = (const float*)d_in[3];
    const float* W1 = (const float*)d_in[4];
    const float* b1 = (const float*)d_in[5];
    const float* W2 = (const float*)d_in[6];
    const float* b2 = (const float*)d_in[7];
    const float* W3 = (const float*)d_in[8];
    float* out = (float*)d_out;

    const int n = in_sizes[1] / 16;

    transposeW<<<(HID * HID + 255) / 256, 256>>>(W1, W2);

    const int blocks = (n + SB - 1) / SB;
    lnn_kernel<<<blocks, NTH>>>(z, W0, b0, W1, b1, W2, b2, W3, out, n);
}

// round 9
// speedup vs baseline: 1.3495x; 1.1151x over previous
#include <cuda_runtime.h>
#include <cstdint>

#define HID  200
#define DD   8
#define SB   8            // samples per block
#define CG   25           // column groups (25 * 8 = 200 cols)
#define NC   8            // columns per thread
#define NTH  224          // 8 samples * 25 groups (+24 idle) = 7 warps
#define NW   7
#define SLOT 12           // floats per (col,sample) record (9 used)
#define PADK 100          // floats per col row: SB*SLOT=96 +4 pad (bank stagger)
#define EPSV 0.1f
#define DSMEM (HID * PADK * 4)   // 80000 bytes

// Pre-transposed weights (device scratch; no allocation)
__device__ float g_W1T[HID * HID];
__device__ float g_W2T[HID * HID];

__global__ void transposeW(const float* __restrict__ W1, const float* __restrict__ W2) {
    int idx = blockIdx.x * blockDim.x + threadIdx.x;
    if (idx < HID * HID) {
        int r = idx / HID, c = idx % HID;
        g_W1T[c * HID + r] = W1[idx];
        g_W2T[c * HID + r] = W2[idx];
    }
}

typedef unsigned long long u64;

__device__ __forceinline__ u64 pack2(float lo, float hi) {
    u64 r; asm("mov.b64 %0, {%1, %2};" : "=l"(r) : "f"(lo), "f"(hi)); return r;
}
__device__ __forceinline__ float2 unpack2(u64 v) {
    float2 r; asm("mov.b64 {%0, %1}, %2;" : "=f"(r.x), "=f"(r.y) : "l"(v)); return r;
}
__device__ __forceinline__ u64 fma2(u64 a, u64 b, u64 c) {
    u64 d; asm("fma.rn.f32x2 %0, %1, %2, %3;" : "=l"(d) : "l"(a), "l"(b), "l"(c)); return d;
}

__device__ __forceinline__ float sigm(float x)     { return 1.0f / (1.0f + expf(-x)); }
__device__ __forceinline__ float softplusf(float x){ return fmaxf(x, 0.0f) + log1pf(expf(-fabsf(x))); }

// GEMM phase: Cp[r][j] (r=0..7 tangent rows, r=8 primal row; j = col-pair)
//   Cp[r][j] += sum_k  A[s][k][r] * W[k][col0 + 2j .. 2j+1]
// A read from db (slots 0..8), W streamed via LDG.128 (L2/L1 resident).
#define GEMM_PHASE(Wb, Cp)                                                      \
    {                                                                           \
        _Pragma("unroll")                                                       \
        for (int r = 0; r < 9; r++) {                                           \
            _Pragma("unroll")                                                   \
            for (int j = 0; j < 4; j++) Cp[r][j] = 0ull;                        \
        }                                                                       \
        _Pragma("unroll 2")                                                     \
        for (int k = 0; k < HID; k++) {                                         \
            const float* ap = &db[k * PADK + s * SLOT];                         \
            float4 a0 = *reinterpret_cast<const float4*>(ap);                   \
            float4 a1 = *reinterpret_cast<const float4*>(ap + 4);               \
            float  a8 = ap[8];                                                  \
            float4 w0 = *reinterpret_cast<const float4*>(&(Wb)[k * HID + col0]);     \
            float4 w1 = *reinterpret_cast<const float4*>(&(Wb)[k * HID + col0 + 4]); \
            u64 uw0 = pack2(w0.x, w0.y), uw1 = pack2(w0.z, w0.w);               \
            u64 uw2 = pack2(w1.x, w1.y), uw3 = pack2(w1.z, w1.w);               \
            float av[9] = {a0.x, a0.y, a0.z, a0.w, a1.x, a1.y, a1.z, a1.w, a8}; \
            _Pragma("unroll")                                                   \
            for (int r = 0; r < 9; r++) {                                       \
                u64 ab = pack2(av[r], av[r]);                                   \
                Cp[r][0] = fma2(ab, uw0, Cp[r][0]);                             \
                Cp[r][1] = fma2(ab, uw1, Cp[r][1]);                             \
                Cp[r][2] = fma2(ab, uw2, Cp[r][2]);                             \
                Cp[r][3] = fma2(ab, uw3, Cp[r][3]);                             \
            }                                                                   \
        }                                                                       \
    }

__global__ void __launch_bounds__(NTH, 2) lnn_kernel(
    const float* __restrict__ z,
    const float* __restrict__ W0, const float* __restrict__ b0,
    const float* __restrict__ W1, const float* __restrict__ b1,
    const float* __restrict__ W2, const float* __restrict__ b2,
    const float* __restrict__ W3,
    float* __restrict__ out, int n)
{
    extern __shared__ float db[];          // [HID][PADK]: per hidden-col, 8 samples x 12 slots
    __shared__ float shz[SB][16];
    __shared__ float sh_g[SB][16];
    __shared__ float sh_H[SB][8][16];

    const int tid  = threadIdx.x;
    const int s    = tid & 7;              // sample within block
    const int g    = tid >> 3;             // column group
    const int col0 = g * NC;
    const bool act = (g < CG);
    const int base = blockIdx.x * SB;
    const int warp = tid >> 5, lane = tid & 31;

    // load z (clamped for tail safety)
    for (int i = tid; i < SB * 16; i += NTH) {
        int smp = base + (i >> 4);
        if (smp >= n) smp = n - 1;
        shz[i >> 4][i & 15] = z[smp * 16 + (i & 15)];
    }
    __syncthreads();

    float s1r[NC], s2r[NC];
    u64 Cp[9][4];

    // ---------- phase 0: x1 = z@W0 + b0 ; seed tangents ----------
    if (act) {
        float xa[NC];
        *reinterpret_cast<float4*>(&xa[0]) = *reinterpret_cast<const float4*>(&b0[col0]);
        *reinterpret_cast<float4*>(&xa[4]) = *reinterpret_cast<const float4*>(&b0[col0 + 4]);
        #pragma unroll
        for (int m = 0; m < 16; m++) {
            float zm = shz[s][m];
            float wv[NC];
            *reinterpret_cast<float4*>(&wv[0]) = *reinterpret_cast<const float4*>(&W0[m * HID + col0]);
            *reinterpret_cast<float4*>(&wv[4]) = *reinterpret_cast<const float4*>(&W0[m * HID + col0 + 4]);
            #pragma unroll
            for (int c = 0; c < NC; c++) xa[c] = fmaf(zm, wv[c], xa[c]);
        }
        #pragma unroll
        for (int c = 0; c < NC; c++) {
            s1r[c] = sigm(xa[c]);
            db[(col0 + c) * PADK + s * SLOT + 8] = softplusf(xa[c]);  // h1
        }
        #pragma unroll
        for (int d = 0; d < DD; d++) {
            float wv[NC];
            *reinterpret_cast<float4*>(&wv[0]) = *reinterpret_cast<const float4*>(&W0[(DD + d) * HID + col0]);
            *reinterpret_cast<float4*>(&wv[4]) = *reinterpret_cast<const float4*>(&W0[(DD + d) * HID + col0 + 4]);
            #pragma unroll
            for (int c = 0; c < NC; c++)
                db[(col0 + c) * PADK + s * SLOT + d] = s1r[c] * wv[c];  // th1
        }
    }
    __syncthreads();

    // ---------- phase 1: stream W1 -> x2 (row 8) + t2 (rows 0..7) ----------
    if (act) { GEMM_PHASE(W1, Cp); }
    __syncthreads();
    if (act) {
        float bw[NC];
        *reinterpret_cast<float4*>(&bw[0]) = *reinterpret_cast<const float4*>(&b1[col0]);
        *reinterpret_cast<float4*>(&bw[4]) = *reinterpret_cast<const float4*>(&b1[col0 + 4]);
        #pragma unroll
        for (int j = 0; j < 4; j++) {
            float2 xp = unpack2(Cp[8][j]);
            float xlo = xp.x + bw[2 * j], xhi = xp.y + bw[2 * j + 1];
            float slo = sigm(xlo), shi = sigm(xhi);
            s2r[2 * j] = slo; s2r[2 * j + 1] = shi;
            float vlo[9], vhi[9];
            #pragma unroll
            for (int d = 0; d < DD; d++) {
                float2 t = unpack2(Cp[d][j]);
                vlo[d] = slo * t.x; vhi[d] = shi * t.y;     // th2 = s2*t2
            }
            vlo[8] = softplusf(xlo); vhi[8] = softplusf(xhi);  // h2
            float* plo = &db[(col0 + 2 * j) * PADK + s * SLOT];
            float* phi = &db[(col0 + 2 * j + 1) * PADK + s * SLOT];
            *reinterpret_cast<float4*>(plo)     = make_float4(vlo[0], vlo[1], vlo[2], vlo[3]);
            *reinterpret_cast<float4*>(plo + 4) = make_float4(vlo[4], vlo[5], vlo[6], vlo[7]);
            plo[8] = vlo[8];
            *reinterpret_cast<float4*>(phi)     = make_float4(vhi[0], vhi[1], vhi[2], vhi[3]);
            *reinterpret_cast<float4*>(phi + 4) = make_float4(vhi[4], vhi[5], vhi[6], vhi[7]);
            phi[8] = vhi[8];
        }
    }
    __syncthreads();

    // ---------- phase 2: stream W2 -> x3 + t3 ----------
    if (act) { GEMM_PHASE(W2, Cp); }
    __syncthreads();
    if (act) {
        float bw[NC], w3v[NC];
        *reinterpret_cast<float4*>(&bw[0])  = *reinterpret_cast<const float4*>(&b2[col0]);
        *reinterpret_cast<float4*>(&bw[4])  = *reinterpret_cast<const float4*>(&b2[col0 + 4]);
        *reinterpret_cast<float4*>(&w3v[0]) = *reinterpret_cast<const float4*>(&W3[col0]);
        *reinterpret_cast<float4*>(&w3v[4]) = *reinterpret_cast<const float4*>(&W3[col0 + 4]);
        #pragma unroll
        for (int j = 0; j < 4; j++) {
            float2 xp = unpack2(Cp[8][j]);
            float xlo = xp.x + bw[2 * j], xhi = xp.y + bw[2 * j + 1];
            float slo = sigm(xlo), shi = sigm(xhi);
            float clo = w3v[2 * j] * slo * (1.0f - slo);
            float chi = w3v[2 * j + 1] * shi * (1.0f - shi);
            float vlo[9], vhi[9];
            #pragma unroll
            for (int d = 0; d < DD; d++) {
                float2 t = unpack2(Cp[d][j]);
                vlo[d] = clo * t.x; vhi[d] = chi * t.y;     // delta-d3
            }
            vlo[8] = w3v[2 * j] * slo; vhi[8] = w3v[2 * j + 1] * shi;   // d3
            float* plo = &db[(col0 + 2 * j) * PADK + s * SLOT];
            float* phi = &db[(col0 + 2 * j + 1) * PADK + s * SLOT];
            *reinterpret_cast<float4*>(plo)     = make_float4(vlo[0], vlo[1], vlo[2], vlo[3]);
            *reinterpret_cast<float4*>(plo + 4) = make_float4(vlo[4], vlo[5], vlo[6], vlo[7]);
            plo[8] = vlo[8];
            *reinterpret_cast<float4*>(phi)     = make_float4(vhi[0], vhi[1], vhi[2], vhi[3]);
            *reinterpret_cast<float4*>(phi + 4) = make_float4(vhi[4], vhi[5], vhi[6], vhi[7]);
            phi[8] = vhi[8];
        }
    }
    __syncthreads();

    // ---------- phase 3: stream W2^T -> u2 + r2 ----------
    if (act) { GEMM_PHASE(g_W2T, Cp); }
    __syncthreads();
    if (act) {
        // delta-d2 = s2*r2 + (1-s2)*u2*th2   (th2 still in db; read before overwrite)
        #pragma unroll
        for (int j = 0; j < 4; j++) {
            float2 up = unpack2(Cp[8][j]);     // u2 pair
            float slo = s2r[2 * j], shi = s2r[2 * j + 1];
            float klo = (1.0f - slo) * up.x, khi = (1.0f - shi) * up.y;
            float* plo = &db[(col0 + 2 * j) * PADK + s * SLOT];
            float* phi = &db[(col0 + 2 * j + 1) * PADK + s * SLOT];
            float tlo[8], thi[8];
            *reinterpret_cast<float4*>(&tlo[0]) = *reinterpret_cast<const float4*>(plo);
            *reinterpret_cast<float4*>(&tlo[4]) = *reinterpret_cast<const float4*>(plo + 4);
            *reinterpret_cast<float4*>(&thi[0]) = *reinterpret_cast<const float4*>(phi);
            *reinterpret_cast<float4*>(&thi[4]) = *reinterpret_cast<const float4*>(phi + 4);
            float vlo[9], vhi[9];
            #pragma unroll
            for (int d = 0; d < DD; d++) {
                float2 r = unpack2(Cp[d][j]);
                vlo[d] = fmaf(slo, r.x, klo * tlo[d]);
                vhi[d] = fmaf(shi, r.y, khi * thi[d]);
            }
            vlo[8] = slo * up.x; vhi[8] = shi * up.y;   // d2
            *reinterpret_cast<float4*>(plo)     = make_float4(vlo[0], vlo[1], vlo[2], vlo[3]);
            *reinterpret_cast<float4*>(plo + 4) = make_float4(vlo[4], vlo[5], vlo[6], vlo[7]);
            plo[8] = vlo[8];
            *reinterpret_cast<float4*>(phi)     = make_float4(vhi[0], vhi[1], vhi[2], vhi[3]);
            *reinterpret_cast<float4*>(phi + 4) = make_float4(vhi[4], vhi[5], vhi[6], vhi[7]);
            phi[8] = vhi[8];
        }
    }
    __syncthreads();

    // ---------- phase 4: stream W1^T -> u1 + r1 ----------
    if (act) { GEMM_PHASE(g_W1T, Cp); }
    __syncthreads();
    if (act) {
        // delta-d1 = s1*r1 + s1*(1-s1)*u1*W0[8+d,:] ; d1 = s1*u1
        float u1[NC], co[NC];
        #pragma unroll
        for (int j = 0; j < 4; j++) {
            float2 up = unpack2(Cp[8][j]);
            u1[2 * j] = up.x; u1[2 * j + 1] = up.y;
        }
        #pragma unroll
        for (int c = 0; c < NC; c++) {
            co[c] = s1r[c] * (1.0f - s1r[c]) * u1[c];
            db[(col0 + c) * PADK + s * SLOT + 8] = s1r[c] * u1[c];   // d1
        }
        #pragma unroll
        for (int d = 0; d < DD; d++) {
            float wv[NC];
            *reinterpret_cast<float4*>(&wv[0]) = *reinterpret_cast<const float4*>(&W0[(DD + d) * HID + col0]);
            *reinterpret_cast<float4*>(&wv[4]) = *reinterpret_cast<const float4*>(&W0[(DD + d) * HID + col0 + 4]);
            #pragma unroll
            for (int j = 0; j < 4; j++) {
                float2 r = unpack2(Cp[d][j]);
                db[(col0 + 2 * j) * PADK + s * SLOT + d]     = fmaf(s1r[2 * j],     r.x, co[2 * j]     * wv[2 * j]);
                db[(col0 + 2 * j + 1) * PADK + s * SLOT + d] = fmaf(s1r[2 * j + 1], r.y, co[2 * j + 1] * wv[2 * j + 1]);
            }
        }
    }
    __syncthreads();

    // ---------- final dots ----------
    // gradient: g[m] = sum_k W0[m,k] * d1[k]
    for (int idx = warp; idx < SB * 16; idx += NW) {
        int ss = idx >> 4, m = idx & 15;
        float a = 0.0f;
        for (int k = lane; k < HID; k += 32)
            a = fmaf(W0[m * HID + k], db[k * PADK + ss * SLOT + 8], a);
        #pragma unroll
        for (int off = 16; off > 0; off >>= 1) a += __shfl_xor_sync(0xffffffffu, a, off);
        if (lane == 0) sh_g[ss][m] = a;
    }
    // Hessian rows: H[8+d][m] = sum_k W0[m,k] * delta-d1[d][k]
    for (int idx = warp; idx < SB * 128; idx += NW) {
        int ss = idx >> 7;
        int r = idx & 127;
        int d = r >> 4, m = r & 15;
        float a = 0.0f;
        for (int k = lane; k < HID; k += 32)
            a = fmaf(W0[m * HID + k], db[k * PADK + ss * SLOT + d], a);
        #pragma unroll
        for (int off = 16; off > 0; off >>= 1) a += __shfl_xor_sync(0xffffffffu, a, off);
        if (lane == 0) sh_H[ss][d][m] = a;
    }
    __syncthreads();

    // ---------- per-sample 8x8 solve + output ----------
    if (tid < SB && base + tid < n) {
        const int ss = tid;
        float Mt[DD][DD], Fv[DD], av[DD], vv[DD];
        #pragma unroll
        for (int c = 0; c < DD; c++) vv[c] = shz[ss][DD + c];
        for (int r = 0; r < DD; r++)
            for (int c = 0; c < DD; c++)
                Mt[r][c] = sh_H[ss][r][DD + c] + ((r == c) ? 2.0f * EPSV : 0.0f);
        for (int p = 0; p < DD; p++) {
            float f = sh_g[ss][p];
            for (int c = 0; c < DD; c++) f -= sh_H[ss][p][c] * vv[c];
            Fv[p] = f;
        }
        for (int col = 0; col < DD; col++) {
            int piv = col; float best = fabsf(Mt[col][col]);
            for (int r = col + 1; r < DD; r++) {
                float m = fabsf(Mt[r][col]);
                if (m > best) { best = m; piv = r; }
            }
            if (piv != col) {
                for (int c = col; c < DD; c++) { float t = Mt[col][c]; Mt[col][c] = Mt[piv][c]; Mt[piv][c] = t; }
                float t = Fv[col]; Fv[col] = Fv[piv]; Fv[piv] = t;
            }
            float inv = 1.0f / Mt[col][col];
            for (int r = col + 1; r < DD; r++) {
                float fac = Mt[r][col] * inv;
                for (int c = col; c < DD; c++) Mt[r][c] -= fac * Mt[col][c];
                Fv[r] -= fac * Fv[col];
            }
        }
        for (int r = DD - 1; r >= 0; r--) {
            float x = Fv[r];
            for (int c = r + 1; c < DD; c++) x -= Mt[r][c] * av[c];
            av[r] = x / Mt[r][r];
        }
        const int gi = (base + ss) * 16;
        #pragma unroll
        for (int j = 0; j < DD; j++) out[gi + j] = vv[j];
        #pragma unroll
        for (int j = 0; j < DD; j++) out[gi + DD + j] = av[j];
    }
}

extern "C" void kernel_launch(void* const* d_in, const int* in_sizes, int n_in,
                              void* d_out, int out_size) {
    const float* z  = (const float*)d_in[1];
    const float* W0 = (const float*)d_in[2];
    const float* b0 = (const float*)d_in[3];
    const float* W1 = (const float*)d_in[4];
    const float* b1 = (const float*)d_in[5];
    const float* W2 = (const float*)d_in[6];
    const float* b2 = (const float*)d_in[7];
    const float* W3 = (const float*)d_in[8];
    float* out = (float*)d_out;

    const int n = in_sizes[1] / 16;

    cudaFuncSetAttribute(lnn_kernel, cudaFuncAttributeMaxDynamicSharedMemorySize, DSMEM);

    transposeW<<<(HID * HID + 255) / 256, 256>>>(W1, W2);

    const int blocks = (n + SB - 1) / SB;
    lnn_kernel<<<blocks, NTH, DSMEM>>>(z, W0, b0, W1, b1, W2, b2, W3, out, n);
}